// round 1
// baseline (speedup 1.0000x reference)
#include <cuda_runtime.h>
#include <math_constants.h>
#include <cstdint>

// Problem constants: votes (16,6,6,3,3,32,32,4,4)
#define NPOS   576          // B*H*W
#define KHW    9            // KH*KW
#define II     32           // input capsules
#define OO     32           // output capsules
#define AA16   16           // A*A pose entries
#define KDIM   (KHW*II)     // 288 reduction terms per (pos, o, aa)
#define PERPOS (KDIM*OO*AA16) // 147456 floats per position
#define EPSC   1e-7f
#define INVT1  0.0005f        // 0.01*(1-0.95^1)
#define INVT2  0.00142625f    // 0.01*(1-0.95^3)

// dynamic smem layout (floats):
//   s_R1   [288]   R after M-step1 mixing (per k, o-independent)
//   s_a8   [288]   0.8 * activation
//   s_lnajc0[32]   log(a_j1+eps) - sum_aa log(2*pi*sigma1+eps)   (per o)
//   s_logden[32]   logsumexp over (kh,kw,o) per i
//   s_S1   [32]    (slot 0 used)
//   s_ln   [288*32] log_num, later overwritten in place with R2
#define SMEM_FLOATS (KDIM + KDIM + 32 + 32 + 32 + KDIM*OO)
#define SMEM_REQ_BYTES (120*1024)   // > 114KB forces 1 CTA/SM for L2 residency

extern __shared__ float smem[];

__global__ __launch_bounds__(512, 1)
void em_routing_kernel(const float* __restrict__ votes,
                       const float* __restrict__ activ,
                       const float* __restrict__ beta_a,
                       const float* __restrict__ beta_u,
                       float* __restrict__ out)
{
    float* s_R1     = smem;
    float* s_a8     = s_R1 + KDIM;
    float* s_lnajc0 = s_a8 + KDIM;
    float* s_logden = s_lnajc0 + 32;
    float* s_S1     = s_logden + 32;
    float* s_ln     = s_S1 + 32;

    const int pos = blockIdx.x;
    const int t   = threadIdx.x;        // 0..511
    const int o   = t >> 4;             // 0..31
    const int aa  = t & 15;             // 0..15
    const float* __restrict__ V  = votes + (int64_t)pos * PERPOS;
    const float* __restrict__ Ai = activ + pos * KDIM;

    // ---- prologue: R1 = (0.8*a + 0.2)/32, S1 = sum R1 ----
    if (t < KDIM) {
        float a = Ai[t];
        s_a8[t] = 0.8f * a;
        s_R1[t] = (0.8f * a + 0.2f) * (1.0f / 32.0f);
    }
    __syncthreads();
    if (t < 32) {
        float s = 0.f;
        #pragma unroll
        for (int k = t; k < KDIM; k += 32) s += s_R1[k];
        #pragma unroll
        for (int off = 16; off; off >>= 1) s += __shfl_xor_sync(0xffffffffu, s, off);
        if (t == 0) s_S1[0] = s;
    }
    __syncthreads();
    const float S1 = s_S1[0];

    // ---- Pass A (M-step 1): accumulate sum(R1*V), sum(R1*V^2) for own (o,aa) ----
    float av = 0.f, av2 = 0.f;
    {
        const float* p = V + t;
        #pragma unroll 8
        for (int k = 0; k < KDIM; ++k) {
            float v  = p[(size_t)k * 512];
            float r  = s_R1[k];
            float rv = r * v;
            av  += rv;
            av2  = fmaf(rv, v, av2);
        }
    }
    const float invS1 = 1.0f / (S1 + EPSC);
    const float mu1   = av * invS1;
    // sum R(V-mu)^2 = av2 - 2*mu*av + mu^2*S1
    const float sig1  = fmaf(mu1 * mu1, S1, fmaf(-2.0f * mu1, av, av2)) * invS1;
    const float i2s1  = 0.5f / sig1;   // reference divides by 2*sigma (no eps)

    // per-o reductions over the 16 aa lanes
    float c0   = __logf(fmaf(2.0f * CUDART_PI_F, sig1, EPSC));
    float cost = (beta_u[o] - 0.5f * __logf(sig1 + EPSC)) * S1;
    #pragma unroll
    for (int off = 8; off; off >>= 1) {
        c0   += __shfl_xor_sync(0xffffffffu, c0, off);
        cost += __shfl_xor_sync(0xffffffffu, cost, off);
    }
    if (aa == 0) {
        float arg = INVT1 * (beta_a[o] - cost);
        float aj  = 1.0f / (1.0f + __expf(-arg));
        s_lnajc0[o] = __logf(aj + EPSC) - c0;
    }
    __syncthreads();

    // ---- Pass B (E-step): log_num[k][o] into SMEM ----
    {
        const float lnajc0 = s_lnajc0[o];
        const float* p = V + t;
        #pragma unroll 4
        for (int k = 0; k < KDIM; ++k) {
            float v = p[(size_t)k * 512];
            float d = v - mu1;
            float term = d * d * i2s1;
            #pragma unroll
            for (int off = 8; off; off >>= 1)
                term += __shfl_xor_sync(0xffffffffu, term, off);
            if (aa == 0) s_ln[k * OO + o] = lnajc0 - term;
        }
    }
    __syncthreads();

    // ---- logsumexp over (kh,kw,o) per i; warp w handles i = w, w+16 ----
    {
        const int wid = t >> 5, lane = t & 31;
        for (int i = wid; i < II; i += 16) {
            float x[KHW];
            float m = -CUDART_INF_F;
            #pragma unroll
            for (int kk = 0; kk < KHW; ++kk) {
                x[kk] = s_ln[(kk * II + i) * OO + lane];
                m = fmaxf(m, x[kk]);
            }
            #pragma unroll
            for (int off = 16; off; off >>= 1)
                m = fmaxf(m, __shfl_xor_sync(0xffffffffu, m, off));
            float s = 0.f;
            #pragma unroll
            for (int kk = 0; kk < KHW; ++kk) s += __expf(x[kk] - m);
            #pragma unroll
            for (int off = 16; off; off >>= 1)
                s += __shfl_xor_sync(0xffffffffu, s, off);
            if (lane == 0) s_logden[i] = m + __logf(s);
        }
    }
    __syncthreads();

    // ---- convert log_num -> R2 in place: R2 = 0.8*a*exp(ln - logden[i]) + 0.2*R1 ----
    for (int p = t; p < KDIM * OO; p += 512) {
        int k = p >> 5;          // k index (kh,kw,i)
        int i = k & 31;          // i is innermost of k
        float r = fmaf(s_a8[k], __expf(s_ln[p] - s_logden[i]), 0.2f * s_R1[k]);
        s_ln[p] = r;
    }
    __syncthreads();

    // ---- Pass C (M-step 2): accumulate sum R2, sum R2*V, sum R2*V^2 ----
    float cr = 0.f, crv = 0.f, crv2 = 0.f;
    {
        const float* p  = V + t;
        const float* rr = s_ln + o;
        #pragma unroll 8
        for (int k = 0; k < KDIM; ++k) {
            float v  = p[(size_t)k * 512];
            float r  = rr[k * OO];      // broadcast across the 16 aa lanes
            float rv = r * v;
            cr  += r;
            crv += rv;
            crv2 = fmaf(rv, v, crv2);
        }
    }
    const float invR = 1.0f / (cr + EPSC);
    const float mu2  = crv * invR;
    out[pos * 512 + t] = mu2;           // poses (b,h,w,o,a,a)

    const float sig2 = fmaf(mu2 * mu2, cr, fmaf(-2.0f * mu2, crv, crv2)) * invR;
    float cost2 = (beta_u[o] - 0.5f * __logf(sig2 + EPSC)) * cr;
    #pragma unroll
    for (int off = 8; off; off >>= 1)
        cost2 += __shfl_xor_sync(0xffffffffu, cost2, off);
    if (aa == 0) {
        float arg = INVT2 * (beta_a[o] - cost2);
        out[NPOS * 512 + pos * OO + o] = 1.0f / (1.0f + __expf(-arg)); // acts
    }
}

extern "C" void kernel_launch(void* const* d_in, const int* in_sizes, int n_in,
                              void* d_out, int out_size) {
    const float* votes  = (const float*)d_in[0];
    const float* activ  = (const float*)d_in[1];
    const float* beta_a = (const float*)d_in[2];
    const float* beta_u = (const float*)d_in[3];

    // Oversized dynamic smem (> 114 KB) forces occupancy 1 so the 148
    // concurrent CTAs' 576KB vote slabs (85 MB) stay L2-resident across
    // the 3 passes. Idempotent; ignore error if called during capture.
    cudaFuncSetAttribute(em_routing_kernel,
                         cudaFuncAttributeMaxDynamicSharedMemorySize,
                         SMEM_REQ_BYTES);

    em_routing_kernel<<<NPOS, 512, SMEM_REQ_BYTES>>>(
        votes, activ, beta_a, beta_u, (float*)d_out);
}

// round 2
// speedup vs baseline: 2.0063x; 2.0063x over previous
#include <cuda_runtime.h>
#include <math_constants.h>
#include <cstdint>

// Problem constants: votes (16,6,6,3,3,32,32,4,4)
#define NPOS   576            // B*H*W
#define KHW    9              // KH*KW
#define II     32             // input capsules
#define OO     32             // output capsules
#define AA16   16             // A*A pose entries
#define KDIM   (KHW*II)       // 288 reduction terms per (pos, o, aa)
#define KHALF  144
#define PERPOS (KDIM*OO*AA16) // 147456 floats per position
#define EPSC   1e-7f
#define INVT1  0.0005f        // 0.01*(1-0.95^1)
#define INVT2  0.00142625f    // 0.01*(1-0.95^3)

// Force 1 CTA/SM (>114KB) so 148 concurrent CTAs * 576KB = 85MB stays L2-resident
#define SMEM_REQ_BYTES (120*1024)

extern __shared__ float smem[];

__global__ __launch_bounds__(1024, 1)
void em_routing_kernel(const float* __restrict__ votes,
                       const float* __restrict__ activ,
                       const float* __restrict__ beta_a,
                       const float* __restrict__ beta_u,
                       float* __restrict__ out)
{
    // smem layout (floats)
    float* s_R1     = smem;            // 288
    float* s_a8     = s_R1 + KDIM;     // 288
    float* s_q2T    = s_a8 + KDIM;     // 512  [aa][o] = 1/(2*sigma1)
    float* s_mq1T   = s_q2T + 512;     // 512  [aa][o] = -2*mu1/(2*sigma1)
    float* s_base   = s_mq1T + 512;    // 32   per-o log_num constant
    float* s_logden = s_base + 32;     // 32
    float* s_S1     = s_logden + 32;   // 1
    float* s_pA     = s_S1 + 1;        // 1024 (pass A partials)
    float* s_pC     = s_pA + 1024;     // 1536 (pass C partials)
    float* s_ln     = s_pC + 1536;     // 9216 log_num -> R2

    const int pos = blockIdx.x;
    const int t   = threadIdx.x;         // 0..1023
    const int c   = t & 511;             // column o*16+aa
    const int kb  = (t >> 9) * KHALF;    // k chunk base (0 or 144)
    const float* __restrict__ V  = votes + (int64_t)pos * PERPOS;
    const float* __restrict__ Ai = activ + pos * KDIM;

    // ---- prologue: R1 = (0.8*a + 0.2)/32 ----
    if (t < KDIM) {
        float a = Ai[t];
        s_a8[t] = 0.8f * a;
        s_R1[t] = (0.8f * a + 0.2f) * (1.0f / 32.0f);
    }
    __syncthreads();
    if (t < 32) {   // warp 0: S1 = sum R1 (visible after next barrier)
        float s = 0.f;
        #pragma unroll
        for (int k = t; k < KDIM; k += 32) s += s_R1[k];
        #pragma unroll
        for (int off = 16; off; off >>= 1) s += __shfl_xor_sync(0xffffffffu, s, off);
        if (t == 0) s_S1[0] = s;
    }

    // ---- Pass A (M-step 1): half-k sums of R1*V, R1*V^2 per (o,aa) ----
    float av = 0.f, av2 = 0.f;
    {
        const float* p = V + c + (size_t)kb * 512;
        #pragma unroll 16
        for (int k = 0; k < KHALF; ++k) {
            float v  = p[(size_t)k * 512];
            float r  = s_R1[kb + k];
            float rv = r * v;
            av  += rv;
            av2  = fmaf(rv, v, av2);
        }
    }
    if (t >= 512) { s_pA[c] = av; s_pA[512 + c] = av2; }
    __syncthreads();

    if (t < 512) {
        av  += s_pA[c];
        av2 += s_pA[512 + c];
        const float S1    = s_S1[0];
        const int   o     = c >> 4;
        const int   aa    = c & 15;
        const float invS1 = 1.0f / (S1 + EPSC);
        const float mu1   = av * invS1;
        const float sig1  = fmaf(mu1 * mu1, S1, fmaf(-2.0f * mu1, av, av2)) * invS1;
        const float i2s1  = 0.5f / sig1;          // 1/(2*sigma^2), no eps (matches ref)
        const float q1    = mu1 * i2s1;
        s_q2T [aa * 32 + o] = i2s1;
        s_mq1T[aa * 32 + o] = -2.0f * q1;

        float Co   = mu1 * q1;                                   // mu^2/(2 sigma^2)
        float c0   = __logf(fmaf(2.0f * CUDART_PI_F, sig1, EPSC));
        float cost = (beta_u[o] - 0.5f * __logf(sig1 + EPSC)) * S1;
        #pragma unroll
        for (int off = 8; off; off >>= 1) {
            Co   += __shfl_xor_sync(0xffffffffu, Co,   off);
            c0   += __shfl_xor_sync(0xffffffffu, c0,   off);
            cost += __shfl_xor_sync(0xffffffffu, cost, off);
        }
        if (aa == 0) {
            float arg = INVT1 * (beta_a[o] - cost);
            float aj  = 1.0f / (1.0f + __expf(-arg));
            s_base[o] = __logf(aj + EPSC) - c0 - Co;
        }
    }
    __syncthreads();

    // ---- Pass B (E-step): log_num[k][o], thread-per-(k,o), float4 over aa ----
    {
        const int ob = t & 31;
        float q2r[16], mqr[16];
        #pragma unroll
        for (int a = 0; a < 16; ++a) {
            q2r[a] = s_q2T [a * 32 + ob];
            mqr[a] = s_mq1T[a * 32 + ob];
        }
        const float base = s_base[ob];
        const int   k0   = t >> 5;
        #pragma unroll 3
        for (int j = 0; j < 9; ++j) {
            const int k = k0 + j * 32;
            const float4* pv = (const float4*)(V + (size_t)k * 512 + ob * 16);
            float term = 0.f;
            #pragma unroll
            for (int g = 0; g < 4; ++g) {
                float4 v = pv[g];
                term = fmaf(v.x, fmaf(v.x, q2r[4*g+0], mqr[4*g+0]), term);
                term = fmaf(v.y, fmaf(v.y, q2r[4*g+1], mqr[4*g+1]), term);
                term = fmaf(v.z, fmaf(v.z, q2r[4*g+2], mqr[4*g+2]), term);
                term = fmaf(v.w, fmaf(v.w, q2r[4*g+3], mqr[4*g+3]), term);
            }
            s_ln[k * OO + ob] = base - term;
        }
    }
    __syncthreads();

    // ---- logsumexp over (kh,kw,o) per i: warp w handles i = w ----
    {
        const int wid = t >> 5, lane = t & 31;
        float x[KHW];
        float m = -CUDART_INF_F;
        #pragma unroll
        for (int kk = 0; kk < KHW; ++kk) {
            x[kk] = s_ln[(kk * II + wid) * OO + lane];
            m = fmaxf(m, x[kk]);
        }
        #pragma unroll
        for (int off = 16; off; off >>= 1)
            m = fmaxf(m, __shfl_xor_sync(0xffffffffu, m, off));
        float s = 0.f;
        #pragma unroll
        for (int kk = 0; kk < KHW; ++kk) s += __expf(x[kk] - m);
        #pragma unroll
        for (int off = 16; off; off >>= 1)
            s += __shfl_xor_sync(0xffffffffu, s, off);
        if (lane == 0) s_logden[wid] = m + __logf(s);
    }
    __syncthreads();

    // ---- log_num -> R2 in place: R2 = 0.8*a*exp(ln - logden[i]) + 0.2*R1 ----
    #pragma unroll
    for (int j = 0; j < 9; ++j) {
        const int pp = t + j * 1024;
        const int k  = pp >> 5;
        const int i  = k & 31;
        s_ln[pp] = fmaf(s_a8[k], __expf(s_ln[pp] - s_logden[i]), 0.2f * s_R1[k]);
    }
    __syncthreads();

    // ---- Pass C (M-step 2): half-k sums of R2, R2*V, R2*V^2 ----
    float cr = 0.f, crv = 0.f, crv2 = 0.f;
    {
        const int o = c >> 4;
        const float* p = V + c + (size_t)kb * 512;
        #pragma unroll 16
        for (int k = 0; k < KHALF; ++k) {
            float v  = p[(size_t)k * 512];
            float r  = s_ln[(kb + k) * OO + o];   // 2 distinct addrs/warp: broadcast
            float rv = r * v;
            cr  += r;
            crv += rv;
            crv2 = fmaf(rv, v, crv2);
        }
    }
    if (t >= 512) { s_pC[c] = cr; s_pC[512 + c] = crv; s_pC[1024 + c] = crv2; }
    __syncthreads();

    if (t < 512) {
        cr   += s_pC[c];
        crv  += s_pC[512 + c];
        crv2 += s_pC[1024 + c];
        const int   o    = c >> 4;
        const float invR = 1.0f / (cr + EPSC);
        const float mu2  = crv * invR;
        out[pos * 512 + c] = mu2;                                // poses

        const float sig2 = fmaf(mu2 * mu2, cr, fmaf(-2.0f * mu2, crv, crv2)) * invR;
        float cost2 = (beta_u[o] - 0.5f * __logf(sig2 + EPSC)) * cr;
        #pragma unroll
        for (int off = 8; off; off >>= 1)
            cost2 += __shfl_xor_sync(0xffffffffu, cost2, off);
        if ((c & 15) == 0) {
            float arg = INVT2 * (beta_a[o] - cost2);
            out[NPOS * 512 + pos * OO + o] = 1.0f / (1.0f + __expf(-arg)); // acts
        }
    }
}

extern "C" void kernel_launch(void* const* d_in, const int* in_sizes, int n_in,
                              void* d_out, int out_size) {
    const float* votes  = (const float*)d_in[0];
    const float* activ  = (const float*)d_in[1];
    const float* beta_a = (const float*)d_in[2];
    const float* beta_u = (const float*)d_in[3];

    cudaFuncSetAttribute(em_routing_kernel,
                         cudaFuncAttributeMaxDynamicSharedMemorySize,
                         SMEM_REQ_BYTES);

    em_routing_kernel<<<NPOS, 1024, SMEM_REQ_BYTES>>>(
        votes, activ, beta_a, beta_u, (float*)d_out);
}